// round 3
// baseline (speedup 1.0000x reference)
#include <cuda_runtime.h>
#include <cuda_bf16.h>
#include <cstdint>

// out[b,s,e] = W_emb[e, tokens[b,s]] + W_pos[s,e]
// tokens: int32 (B,S) = (8,2048)
// W_emb : fp32 (E,V) = (512,50257)   -> gather is strided (stride V) per token
// W_pos : fp32 (S,E) = (2048,512)
// out   : fp32 (B,S,E)

static constexpr int B = 8;
static constexpr int S = 2048;
static constexpr int E = 512;
static constexpr int V = 50257;

static constexpr int E4 = E / 4;                 // 128 float4 per row
static constexpr long long TOTAL4 = (long long)B * S * E4;  // 2,097,152

__global__ __launch_bounds__(256, 8)
void embed_gather_kernel(const int* __restrict__ tokens,
                         const float* __restrict__ W_emb,
                         const float4* __restrict__ W_pos4,
                         float4* __restrict__ out4)
{
    int idx = blockIdx.x * blockDim.x + threadIdx.x;   // [0, TOTAL4)
    // decompose: idx = ((b*S + s) * E4) + e4
    int e4 = idx & (E4 - 1);
    int bs = idx >> 7;            // b*S + s  (E4 = 128 = 2^7)
    int s  = bs & (S - 1);        // S = 2048 = 2^11

    // token index — uniform across each 128-thread group (broadcast load)
    int tok = __ldg(tokens + bs);

    int e = e4 << 2;
    // 4 scattered gather loads, stride V between them; independent -> MLP=4
    const float* col = W_emb + (long long)e * V + tok;
    float g0 = __ldg(col);
    float g1 = __ldg(col + V);
    float g2 = __ldg(col + 2 * V);
    float g3 = __ldg(col + 3 * V);

    // positional: coalesced float4, reused across batch (L2-resident, 4 MB)
    float4 p = __ldg(W_pos4 + s * E4 + e4);

    float4 r;
    r.x = g0 + p.x;
    r.y = g1 + p.y;
    r.z = g2 + p.z;
    r.w = g3 + p.w;

    // streaming store: write-once 32 MB must not evict the W_emb sector
    // working set (~95 MB) from L2
    __stcs(out4 + idx, r);
}

extern "C" void kernel_launch(void* const* d_in, const int* in_sizes, int n_in,
                              void* d_out, int out_size)
{
    const int*   tokens = (const int*)d_in[0];
    const float* W_emb  = (const float*)d_in[1];
    const float* W_pos  = (const float*)d_in[2];
    float*       out    = (float*)d_out;

    const int threads = 256;
    const int blocks  = (int)(TOTAL4 / threads);   // 8192 blocks, exact
    embed_gather_kernel<<<blocks, threads>>>(tokens, W_emb,
                                             (const float4*)W_pos,
                                             (float4*)out);
}

// round 4
// speedup vs baseline: 1.3445x; 1.3445x over previous
#include <cuda_runtime.h>
#include <cuda_bf16.h>
#include <cstdint>

// out[b,s,e] = W_emb[e, tokens[b,s]] + W_pos[s,e]
// tokens: int32 (B,S) = (8,2048)
// W_emb : fp32 (E,V) = (512,50257)   -> gather is strided (stride V) per token
// W_pos : fp32 (S,E) = (2048,512)
// out   : fp32 (B,S,E)
//
// Key optimization vs R0: phase the grid over E-chunks (blockIdx.y slowest)
// so that each phase's W_emb sector working set (~24 MB for 128 rows) stays
// L2-resident, converting ~270 MB of redundant DRAM sector refetches into L2
// hits. Stores / W_pos loads remain fully coalesced (warp spans 32 float4s
// of one token).

static constexpr int B = 8;
static constexpr int S = 2048;
static constexpr int E = 512;
static constexpr int V = 50257;

static constexpr int E4 = E / 4;                  // 128 float4 per row
static constexpr int E_CHUNK4 = 32;               // 128 floats per E-chunk
static constexpr int N_CHUNKS = E4 / E_CHUNK4;    // 4 phases
static constexpr int TOK_PER_BLOCK = 8;           // 256 threads = 8 tok x 32 e4
static constexpr int BS_TOTAL = B * S;            // 16384 tokens

__global__ __launch_bounds__(256, 8)
void embed_gather_phased_kernel(const int* __restrict__ tokens,
                                const float* __restrict__ W_emb,
                                const float4* __restrict__ W_pos4,
                                float4* __restrict__ out4)
{
    // warp lanes span 32 consecutive e4 -> coalesced stores & W_pos loads
    int lane_e = threadIdx.x & 31;                 // e4 offset within chunk
    int trow   = threadIdx.x >> 5;                 // token slot within block

    int bs = blockIdx.x * TOK_PER_BLOCK + trow;    // [0, 16384)
    int e4 = blockIdx.y * E_CHUNK4 + lane_e;       // chunk is launch-order slowest
    int s  = bs & (S - 1);

    // token index — uniform across the warp (broadcast load)
    int tok = __ldg(tokens + bs);

    int e = e4 << 2;
    // 4 scattered gather loads, stride V apart; independent -> MLP=4.
    // Within a phase, the touched sectors (128 rows x ~5.8K sectors ~ 24 MB)
    // stay L2-resident, so repeated tokens hit L2.
    const float* col = W_emb + (long long)e * V + tok;
    float g0 = __ldg(col);
    float g1 = __ldg(col + V);
    float g2 = __ldg(col + 2 * V);
    float g3 = __ldg(col + 3 * V);

    // positional: coalesced float4; 1 MB slice per phase, L2-hits across batch
    float4 p = __ldg(W_pos4 + s * E4 + e4);

    float4 r;
    r.x = g0 + p.x;
    r.y = g1 + p.y;
    r.z = g2 + p.z;
    r.w = g3 + p.w;

    // streaming store: write-once 32 MB must not evict the phase's W_emb
    // sector working set from L2
    __stcs(out4 + (long long)bs * E4 + e4, r);
}

extern "C" void kernel_launch(void* const* d_in, const int* in_sizes, int n_in,
                              void* d_out, int out_size)
{
    const int*   tokens = (const int*)d_in[0];
    const float* W_emb  = (const float*)d_in[1];
    const float* W_pos  = (const float*)d_in[2];
    float*       out    = (float*)d_out;

    dim3 grid(BS_TOTAL / TOK_PER_BLOCK, N_CHUNKS);   // (2048, 4)
    embed_gather_phased_kernel<<<grid, 256>>>(tokens, W_emb,
                                              (const float4*)W_pos,
                                              (float4*)out);
}